// round 1
// baseline (speedup 1.0000x reference)
#include <cuda_runtime.h>
#include <cuda_bf16.h>

#define N_MAX 100000
#define F 16

// Scratch (allocation-free rule: __device__ globals)
__device__ __align__(16) float g_hs [N_MAX * F];  // prescaled features (scatter source)
__device__ __align__(16) float g_acc[N_MAX * F];  // scatter accumulator
__device__ float g_dinv[N_MAX];
__device__ int   g_deg [N_MAX];

// ---------------------------------------------------------------------------
// Vectorized no-return global reduction (sm_90+): 1 instr per float4
__device__ __forceinline__ void red_add_v4(float* addr, float4 v) {
    asm volatile("red.global.add.v4.f32 [%0], {%1, %2, %3, %4};"
                 :: "l"(addr), "f"(v.x), "f"(v.y), "f"(v.z), "f"(v.w)
                 : "memory");
}

// ---------------------------------------------------------------------------
__global__ void k_deg_init(int n) {
    int i = blockIdx.x * blockDim.x + threadIdx.x;
    if (i < n) g_deg[i] = 1;   // self-loop
}

__global__ void k_deg_count(const int* __restrict__ dst, int E) {
    int e = blockIdx.x * blockDim.x + threadIdx.x;
    if (e < E) atomicAdd(&g_deg[dst[e]], 1);   // ptxas -> RED.E.ADD (no return)
}

// ---------------------------------------------------------------------------
// Per-node transform. layer==1: in = x, compute dinv from deg.
// layer==2: in = relu(g_acc * dinv + b_pre), dinv from g_dinv.
// Writes g_hs[i] = (in @ W) * dinv   and   g_acc[i] = g_hs[i]  (self-loop init)
__global__ void k_transform(const float* __restrict__ xin,
                            const float* __restrict__ W,
                            const float* __restrict__ b_pre,
                            int n, int first) {
    __shared__ float sW[F * F];
    __shared__ float sb[F];
    int t = threadIdx.x;
    if (t < F * F) sW[t] = W[t];
    if (t < F)     sb[t] = first ? 0.0f : b_pre[t];
    __syncthreads();

    int i = blockIdx.x * blockDim.x + t;
    if (i >= n) return;

    float dinv;
    float xv[F];
    if (first) {
        dinv = rsqrtf((float)g_deg[i]);
        g_dinv[i] = dinv;
        const float4* xp = (const float4*)(xin + (size_t)i * F);
        #pragma unroll
        for (int q = 0; q < 4; q++) {
            float4 v = __ldg(xp + q);
            xv[4*q+0] = v.x; xv[4*q+1] = v.y; xv[4*q+2] = v.z; xv[4*q+3] = v.w;
        }
    } else {
        dinv = g_dinv[i];
        const float4* xp = (const float4*)(g_acc + (size_t)i * F);
        #pragma unroll
        for (int q = 0; q < 4; q++) {
            float4 v = xp[q];
            xv[4*q+0] = v.x; xv[4*q+1] = v.y; xv[4*q+2] = v.z; xv[4*q+3] = v.w;
        }
        #pragma unroll
        for (int k = 0; k < F; k++)
            xv[k] = fmaxf(fmaf(xv[k], dinv, sb[k]), 0.0f);   // epilogue of layer 1 + relu
    }

    float h[F];
    #pragma unroll
    for (int j = 0; j < F; j++) {
        float a = 0.0f;
        #pragma unroll
        for (int k = 0; k < F; k++)
            a = fmaf(xv[k], sW[k * F + j], a);
        h[j] = a * dinv;                                     // prescale by dinv[src]
    }

    float4* hp = (float4*)(g_hs  + (size_t)i * F);
    float4* ap = (float4*)(g_acc + (size_t)i * F);
    #pragma unroll
    for (int q = 0; q < 4; q++) {
        float4 v = make_float4(h[4*q], h[4*q+1], h[4*q+2], h[4*q+3]);
        hp[q] = v;
        ap[q] = v;    // self-loop contribution: acc starts at hs[i]
    }
}

// ---------------------------------------------------------------------------
// Edge scatter: acc[dst] += hs[src]. Pure L2 traffic (hs/acc are 6.4MB each).
__global__ void k_scatter(const int* __restrict__ src,
                          const int* __restrict__ dst, int E) {
    int e = blockIdx.x * blockDim.x + threadIdx.x;
    if (e >= E) return;
    int s = src[e];
    int d = dst[e];
    const float4* hp = (const float4*)(g_hs + (size_t)s * F);
    float4 v0 = __ldg(hp + 0);
    float4 v1 = __ldg(hp + 1);
    float4 v2 = __ldg(hp + 2);
    float4 v3 = __ldg(hp + 3);
    float* ap = g_acc + (size_t)d * F;
    red_add_v4(ap +  0, v0);
    red_add_v4(ap +  4, v1);
    red_add_v4(ap +  8, v2);
    red_add_v4(ap + 12, v3);
}

// ---------------------------------------------------------------------------
__global__ void k_finalize(float* __restrict__ out,
                           const float* __restrict__ b, int n) {
    __shared__ float sb[F];
    int t = threadIdx.x;
    if (t < F) sb[t] = b[t];
    __syncthreads();
    int i = blockIdx.x * blockDim.x + t;
    if (i >= n) return;
    float dinv = g_dinv[i];
    const float4* ap = (const float4*)(g_acc + (size_t)i * F);
    float4* op = (float4*)(out + (size_t)i * F);
    #pragma unroll
    for (int q = 0; q < 4; q++) {
        float4 v = ap[q];
        v.x = fmaf(v.x, dinv, sb[4*q+0]);
        v.y = fmaf(v.y, dinv, sb[4*q+1]);
        v.z = fmaf(v.z, dinv, sb[4*q+2]);
        v.w = fmaf(v.w, dinv, sb[4*q+3]);
        op[q] = v;
    }
}

// ---------------------------------------------------------------------------
extern "C" void kernel_launch(void* const* d_in, const int* in_sizes, int n_in,
                              void* d_out, int out_size) {
    const float* x  = (const float*)d_in[0];
    const int*   ei = (const int*)  d_in[1];   // [2, E] int32
    const float* W1 = (const float*)d_in[2];
    const float* b1 = (const float*)d_in[3];
    const float* W2 = (const float*)d_in[4];
    const float* b2 = (const float*)d_in[5];
    float* out = (float*)d_out;

    const int n = in_sizes[0] / F;           // 100000
    const int E = in_sizes[1] / 2;           // 3200000
    const int* src = ei;
    const int* dst = ei + E;

    const int TB = 256;
    const int gn = (n + TB - 1) / TB;
    const int ge = (E + TB - 1) / TB;

    k_deg_init <<<gn, TB>>>(n);
    k_deg_count<<<ge, TB>>>(dst, E);
    // layer 1
    k_transform<<<gn, TB>>>(x, W1, nullptr, n, 1);
    k_scatter  <<<ge, TB>>>(src, dst, E);
    // layer 2 (fused: layer-1 epilogue + relu + W2 transform + prescale)
    k_transform<<<gn, TB>>>(nullptr, W2, b1, n, 0);
    k_scatter  <<<ge, TB>>>(src, dst, E);
    // epilogue
    k_finalize <<<gn, TB>>>(out, b2, n);
}

// round 2
// speedup vs baseline: 1.5495x; 1.5495x over previous
#include <cuda_runtime.h>
#include <cuda_bf16.h>

#define N_MAX 100000
#define F 16

// Scratch (allocation-free rule: __device__ globals)
__device__ __align__(16) float g_hs [N_MAX * F];  // prescaled features (scatter source)
__device__ __align__(16) float g_acc[N_MAX * F];  // scatter accumulator
__device__ float g_dinv[N_MAX];
__device__ int   g_deg [N_MAX];

// ---------------------------------------------------------------------------
// Vectorized no-return global reduction (sm_90+): 1 instr per float4
__device__ __forceinline__ void red_add_v4(float* addr, float4 v) {
    asm volatile("red.global.add.v4.f32 [%0], {%1, %2, %3, %4};"
                 :: "l"(addr), "f"(v.x), "f"(v.y), "f"(v.z), "f"(v.w)
                 : "memory");
}

// ---------------------------------------------------------------------------
__global__ void k_deg_init(int n) {
    int i = blockIdx.x * blockDim.x + threadIdx.x;
    if (i < n) g_deg[i] = 1;   // self-loop
}

// 4 edges per thread via int4 load (dst array is 16B-aligned harness buffer)
__global__ void k_deg_count(const int4* __restrict__ dst4, int E4, int E) {
    int i = blockIdx.x * blockDim.x + threadIdx.x;
    if (i >= E4) return;
    int4 d = __ldg(dst4 + i);
    int base = i * 4;
    if (base + 0 < E) atomicAdd(&g_deg[d.x], 1);
    if (base + 1 < E) atomicAdd(&g_deg[d.y], 1);
    if (base + 2 < E) atomicAdd(&g_deg[d.z], 1);
    if (base + 3 < E) atomicAdd(&g_deg[d.w], 1);
}

// ---------------------------------------------------------------------------
// Per-node transform. first==1: in = x, compute dinv from deg.
// first==0: in = relu(g_acc * dinv + b_pre), dinv from g_dinv.
// Writes g_hs[i] = (in @ W) * dinv   and   g_acc[i] = g_hs[i]  (self-loop init)
__global__ void k_transform(const float* __restrict__ xin,
                            const float* __restrict__ W,
                            const float* __restrict__ b_pre,
                            int n, int first) {
    __shared__ float sW[F * F];
    __shared__ float sb[F];
    int t = threadIdx.x;
    if (t < F * F) sW[t] = W[t];
    if (t < F)     sb[t] = first ? 0.0f : b_pre[t];
    __syncthreads();

    int i = blockIdx.x * blockDim.x + t;
    if (i >= n) return;

    float dinv;
    float xv[F];
    if (first) {
        dinv = rsqrtf((float)g_deg[i]);
        g_dinv[i] = dinv;
        const float4* xp = (const float4*)(xin + (size_t)i * F);
        #pragma unroll
        for (int q = 0; q < 4; q++) {
            float4 v = __ldg(xp + q);
            xv[4*q+0] = v.x; xv[4*q+1] = v.y; xv[4*q+2] = v.z; xv[4*q+3] = v.w;
        }
    } else {
        dinv = g_dinv[i];
        const float4* xp = (const float4*)(g_acc + (size_t)i * F);
        #pragma unroll
        for (int q = 0; q < 4; q++) {
            float4 v = xp[q];
            xv[4*q+0] = v.x; xv[4*q+1] = v.y; xv[4*q+2] = v.z; xv[4*q+3] = v.w;
        }
        #pragma unroll
        for (int k = 0; k < F; k++)
            xv[k] = fmaxf(fmaf(xv[k], dinv, sb[k]), 0.0f);   // epilogue of layer 1 + relu
    }

    float h[F];
    #pragma unroll
    for (int j = 0; j < F; j++) {
        float a = 0.0f;
        #pragma unroll
        for (int k = 0; k < F; k++)
            a = fmaf(xv[k], sW[k * F + j], a);
        h[j] = a * dinv;                                     // prescale by dinv[src]
    }

    float4* hp = (float4*)(g_hs  + (size_t)i * F);
    float4* ap = (float4*)(g_acc + (size_t)i * F);
    #pragma unroll
    for (int q = 0; q < 4; q++) {
        float4 v = make_float4(h[4*q], h[4*q+1], h[4*q+2], h[4*q+3]);
        hp[q] = v;
        ap[q] = v;    // self-loop contribution: acc starts at hs[i]
    }
}

// ---------------------------------------------------------------------------
// Edge scatter: acc[dst] += hs[src].
// 4 lanes per edge -> coalesced 64B row access: one LDG.128 + one RED.128 per
// thread, lanes of an edge contiguous. Cuts L1tex wavefronts ~4x vs 1-thread-
// per-edge; L2 byte/atomic traffic unchanged (L2-resident tables).
__global__ void k_scatter(const int* __restrict__ src,
                          const int* __restrict__ dst, int E) {
    int t = blockIdx.x * blockDim.x + threadIdx.x;
    int e = t >> 2;
    int q = t & 3;
    if (e >= E) return;
    int s = __ldg(src + e);   // 4 lanes read same word -> L1 broadcast
    int d = __ldg(dst + e);
    float4 v = __ldg((const float4*)(g_hs + (size_t)s * F) + q);
    red_add_v4(g_acc + (size_t)d * F + q * 4, v);
}

// ---------------------------------------------------------------------------
__global__ void k_finalize(float* __restrict__ out,
                           const float* __restrict__ b, int n) {
    __shared__ float sb[F];
    int t = threadIdx.x;
    if (t < F) sb[t] = b[t];
    __syncthreads();
    int i = blockIdx.x * blockDim.x + t;
    if (i >= n) return;
    float dinv = g_dinv[i];
    const float4* ap = (const float4*)(g_acc + (size_t)i * F);
    float4* op = (float4*)(out + (size_t)i * F);
    #pragma unroll
    for (int q = 0; q < 4; q++) {
        float4 v = ap[q];
        v.x = fmaf(v.x, dinv, sb[4*q+0]);
        v.y = fmaf(v.y, dinv, sb[4*q+1]);
        v.z = fmaf(v.z, dinv, sb[4*q+2]);
        v.w = fmaf(v.w, dinv, sb[4*q+3]);
        op[q] = v;
    }
}

// ---------------------------------------------------------------------------
extern "C" void kernel_launch(void* const* d_in, const int* in_sizes, int n_in,
                              void* d_out, int out_size) {
    const float* x  = (const float*)d_in[0];
    const int*   ei = (const int*)  d_in[1];   // [2, E] int32
    const float* W1 = (const float*)d_in[2];
    const float* b1 = (const float*)d_in[3];
    const float* W2 = (const float*)d_in[4];
    const float* b2 = (const float*)d_in[5];
    float* out = (float*)d_out;

    const int n = in_sizes[0] / F;           // 100000
    const int E = in_sizes[1] / 2;           // 3200000
    const int* src = ei;
    const int* dst = ei + E;

    const int TB = 256;
    const int gn  = (n + TB - 1) / TB;
    const int E4  = (E + 3) / 4;
    const int ge4 = (E4 + TB - 1) / TB;
    const int ges = (E * 4 + TB - 1) / TB;   // scatter: 4 threads per edge

    k_deg_init <<<gn, TB>>>(n);
    k_deg_count<<<ge4, TB>>>((const int4*)dst, E4, E);
    // layer 1
    k_transform<<<gn, TB>>>(x, W1, nullptr, n, 1);
    k_scatter  <<<ges, TB>>>(src, dst, E);
    // layer 2 (fused: layer-1 epilogue + relu + W2 transform + prescale)
    k_transform<<<gn, TB>>>(nullptr, W2, b1, n, 0);
    k_scatter  <<<ges, TB>>>(src, dst, E);
    // epilogue
    k_finalize <<<gn, TB>>>(out, b2, n);
}

// round 9
// speedup vs baseline: 1.6590x; 1.0707x over previous
#include <cuda_runtime.h>
#include <cuda_bf16.h>

#define N_MAX 100096
#define E_MAX 3200000
#define F 16
#define SCAN_TB 256

// Scratch (allocation-free rule: __device__ globals).
// NOTE: these symbols are referenced from DEVICE code only — passing them as
// host-side kernel arguments yields the host shadow address (R8 bug).
__device__ __align__(16) float g_hs [N_MAX * F];  // prescaled features (gather source)
__device__ __align__(16) float g_acc[N_MAX * F];  // layer-1 aggregation result
__device__ float g_dinv[N_MAX];
__device__ int   g_cnt [N_MAX];    // in-degree (edges only)
__device__ int   g_off [N_MAX];    // CSR row start
__device__ int   g_cur [N_MAX];    // fill cursor
__device__ int   g_esrc[E_MAX];    // src ids grouped by dst
__device__ int   g_bsum[512];      // scan block partials

// ---------------------------------------------------------------------------
__global__ void k_cnt_zero(int n) {
    int i = blockIdx.x * blockDim.x + threadIdx.x;
    if (i < n) g_cnt[i] = 0;
}

// 4 edges per thread via int4 load
__global__ void k_deg_count(const int4* __restrict__ dst4, int E4, int E) {
    int i = blockIdx.x * blockDim.x + threadIdx.x;
    if (i >= E4) return;
    int4 d = __ldg(dst4 + i);
    int base = i * 4;
    if (base + 0 < E) atomicAdd(&g_cnt[d.x], 1);
    if (base + 1 < E) atomicAdd(&g_cnt[d.y], 1);
    if (base + 2 < E) atomicAdd(&g_cnt[d.z], 1);
    if (base + 3 < E) atomicAdd(&g_cnt[d.w], 1);
}

// --------------------------- 3-kernel exclusive scan -----------------------
__global__ void k_scan1(int n) {          // block sums + dinv
    __shared__ int sm[SCAN_TB];
    int t = threadIdx.x;
    int i = blockIdx.x * SCAN_TB + t;
    int c = (i < n) ? g_cnt[i] : 0;
    if (i < n) g_dinv[i] = rsqrtf((float)(c + 1));   // +1 self-loop
    sm[t] = c; __syncthreads();
    #pragma unroll
    for (int s = SCAN_TB / 2; s > 0; s >>= 1) {
        if (t < s) sm[t] += sm[t + s];
        __syncthreads();
    }
    if (t == 0) g_bsum[blockIdx.x] = sm[0];
}

__global__ void k_scan2(int nblk) {       // exclusive scan of <=512 partials
    __shared__ int sm[512];
    int t = threadIdx.x;
    int v = (t < nblk) ? g_bsum[t] : 0;
    sm[t] = v; __syncthreads();
    for (int s = 1; s < 512; s <<= 1) {
        int add = (t >= s) ? sm[t - s] : 0;
        __syncthreads();
        sm[t] += add;
        __syncthreads();
    }
    if (t < nblk) g_bsum[t] = sm[t] - v;  // exclusive
}

__global__ void k_scan3(int n) {          // per-element exclusive offsets
    __shared__ int sm[SCAN_TB];
    int t = threadIdx.x;
    int i = blockIdx.x * SCAN_TB + t;
    int c = (i < n) ? g_cnt[i] : 0;
    sm[t] = c; __syncthreads();
    for (int s = 1; s < SCAN_TB; s <<= 1) {
        int add = (t >= s) ? sm[t - s] : 0;
        __syncthreads();
        sm[t] += add;
        __syncthreads();
    }
    if (i < n) {
        int excl = sm[t] - c + g_bsum[blockIdx.x];
        g_off[i] = excl;
        g_cur[i] = excl;
    }
}

// --------------------------- CSR fill --------------------------------------
__global__ void k_fill(const int4* __restrict__ src4,
                       const int4* __restrict__ dst4, int E4, int E) {
    int i = blockIdx.x * blockDim.x + threadIdx.x;
    if (i >= E4) return;
    int4 s = __ldg(src4 + i);
    int4 d = __ldg(dst4 + i);
    int base = i * 4;
    if (base + 0 < E) g_esrc[atomicAdd(&g_cur[d.x], 1)] = s.x;
    if (base + 1 < E) g_esrc[atomicAdd(&g_cur[d.y], 1)] = s.y;
    if (base + 2 < E) g_esrc[atomicAdd(&g_cur[d.z], 1)] = s.z;
    if (base + 3 < E) g_esrc[atomicAdd(&g_cur[d.w], 1)] = s.w;
}

// ---------------------------------------------------------------------------
// Per-node transform. first==1: in = x.
// first==0: in = relu(g_acc * dinv + b_pre).
// Writes g_hs[i] = (in @ W) * dinv  (prescaled gather source)
__global__ void k_transform(const float* __restrict__ xin,
                            const float* __restrict__ W,
                            const float* __restrict__ b_pre,
                            int n, int first) {
    __shared__ float sW[F * F];
    __shared__ float sb[F];
    int t = threadIdx.x;
    if (t < F * F) sW[t] = W[t];
    if (t < F)     sb[t] = first ? 0.0f : b_pre[t];
    __syncthreads();

    int i = blockIdx.x * blockDim.x + t;
    if (i >= n) return;

    float dinv = g_dinv[i];
    float xv[F];
    const float4* xp = first ? (const float4*)(xin + (size_t)i * F)
                             : (const float4*)(g_acc + (size_t)i * F);
    #pragma unroll
    for (int q = 0; q < 4; q++) {
        float4 v = __ldg(xp + q);
        xv[4*q+0] = v.x; xv[4*q+1] = v.y; xv[4*q+2] = v.z; xv[4*q+3] = v.w;
    }
    if (!first) {
        #pragma unroll
        for (int k = 0; k < F; k++)
            xv[k] = fmaxf(fmaf(xv[k], dinv, sb[k]), 0.0f);  // layer-1 epilogue + relu
    }

    float h[F];
    #pragma unroll
    for (int j = 0; j < F; j++) {
        float a = 0.0f;
        #pragma unroll
        for (int k = 0; k < F; k++)
            a = fmaf(xv[k], sW[k * F + j], a);
        h[j] = a * dinv;                                    // prescale by dinv[src]
    }

    float4* hp = (float4*)(g_hs + (size_t)i * F);
    #pragma unroll
    for (int q = 0; q < 4; q++)
        hp[q] = make_float4(h[4*q], h[4*q+1], h[4*q+2], h[4*q+3]);
}

// ---------------------------------------------------------------------------
// CSR gather: 4 lanes per node accumulate hs[src] in registers, write once.
// No atomics. Unroll x8 -> 8 independent L2 chains per batch (MLP hides the
// ~234-262cyc L2 latency). Index words are lane-broadcast across the 4 lanes
// of a node (conflict-free).
// final_ep==0: write g_acc (device-side symbol reference — NOT a host arg).
// final_ep==1: fuse epilogue out = sum*dinv + b, write harness buffer.
__global__ void k_gather(float* __restrict__ outbuf,
                         const float* __restrict__ b, int n, int final_ep) {
    int t = blockIdx.x * blockDim.x + threadIdx.x;
    int node = t >> 2;
    int q = t & 3;
    if (node >= n) return;
    int off = __ldg(g_off + node);
    int c   = __ldg(g_cnt + node);

    // self-loop: acc starts at hs[node]
    float4 a = __ldg((const float4*)(g_hs + (size_t)node * F) + q);

    const int* ep = g_esrc + off;
    int k = 0;
    for (; k + 8 <= c; k += 8) {
        int s0 = __ldg(ep + k + 0);
        int s1 = __ldg(ep + k + 1);
        int s2 = __ldg(ep + k + 2);
        int s3 = __ldg(ep + k + 3);
        int s4 = __ldg(ep + k + 4);
        int s5 = __ldg(ep + k + 5);
        int s6 = __ldg(ep + k + 6);
        int s7 = __ldg(ep + k + 7);
        float4 v0 = __ldg((const float4*)(g_hs + (size_t)s0 * F) + q);
        float4 v1 = __ldg((const float4*)(g_hs + (size_t)s1 * F) + q);
        float4 v2 = __ldg((const float4*)(g_hs + (size_t)s2 * F) + q);
        float4 v3 = __ldg((const float4*)(g_hs + (size_t)s3 * F) + q);
        float4 v4 = __ldg((const float4*)(g_hs + (size_t)s4 * F) + q);
        float4 v5 = __ldg((const float4*)(g_hs + (size_t)s5 * F) + q);
        float4 v6 = __ldg((const float4*)(g_hs + (size_t)s6 * F) + q);
        float4 v7 = __ldg((const float4*)(g_hs + (size_t)s7 * F) + q);
        a.x += (v0.x + v1.x) + (v2.x + v3.x) + ((v4.x + v5.x) + (v6.x + v7.x));
        a.y += (v0.y + v1.y) + (v2.y + v3.y) + ((v4.y + v5.y) + (v6.y + v7.y));
        a.z += (v0.z + v1.z) + (v2.z + v3.z) + ((v4.z + v5.z) + (v6.z + v7.z));
        a.w += (v0.w + v1.w) + (v2.w + v3.w) + ((v4.w + v5.w) + (v6.w + v7.w));
    }
    for (; k < c; k++) {
        int s = __ldg(ep + k);
        float4 v = __ldg((const float4*)(g_hs + (size_t)s * F) + q);
        a.x += v.x; a.y += v.y; a.z += v.z; a.w += v.w;
    }

    if (final_ep) {
        float dinv = g_dinv[node];
        a.x = fmaf(a.x, dinv, __ldg(b + q * 4 + 0));
        a.y = fmaf(a.y, dinv, __ldg(b + q * 4 + 1));
        a.z = fmaf(a.z, dinv, __ldg(b + q * 4 + 2));
        a.w = fmaf(a.w, dinv, __ldg(b + q * 4 + 3));
        ((float4*)(outbuf + (size_t)node * F))[q] = a;
    } else {
        ((float4*)(g_acc + (size_t)node * F))[q] = a;   // device-side reference
    }
}

// ---------------------------------------------------------------------------
extern "C" void kernel_launch(void* const* d_in, const int* in_sizes, int n_in,
                              void* d_out, int out_size) {
    const float* x  = (const float*)d_in[0];
    const int*   ei = (const int*)  d_in[1];   // [2, E] int32
    const float* W1 = (const float*)d_in[2];
    const float* b1 = (const float*)d_in[3];
    const float* W2 = (const float*)d_in[4];
    const float* b2 = (const float*)d_in[5];
    float* out = (float*)d_out;

    const int n = in_sizes[0] / F;            // 100000
    const int E = in_sizes[1] / 2;            // 3200000
    const int* src = ei;
    const int* dst = ei + E;

    const int TB = 256;
    const int gn   = (n + TB - 1) / TB;
    const int E4   = (E + 3) / 4;
    const int ge4  = (E4 + TB - 1) / TB;
    const int geg  = (n * 4 + TB - 1) / TB;   // gather: 4 threads per node
    const int nblk = (n + SCAN_TB - 1) / SCAN_TB;   // <= 512

    // CSR build (reused by both layers)
    k_cnt_zero <<<gn, TB>>>(n);
    k_deg_count<<<ge4, TB>>>((const int4*)dst, E4, E);
    k_scan1    <<<nblk, SCAN_TB>>>(n);
    k_scan2    <<<1, 512>>>(nblk);
    k_scan3    <<<nblk, SCAN_TB>>>(n);
    k_fill     <<<ge4, TB>>>((const int4*)src, (const int4*)dst, E4, E);

    // layer 1
    k_transform<<<gn, TB>>>(x, W1, nullptr, n, 1);
    k_gather   <<<geg, TB>>>(nullptr, nullptr, n, 0);
    // layer 2 (fused relu/bias/transform; gather fuses final epilogue)
    k_transform<<<gn, TB>>>(nullptr, W2, b1, n, 0);
    k_gather   <<<geg, TB>>>(out, b2, n, 1);
}